// round 2
// baseline (speedup 1.0000x reference)
#include <cuda_runtime.h>

// Problem constants
constexpr int N = 2048;   // sequence length
constexpr int B = 8;      // batch
constexpr int E = 256;    // embed dim (for scores)
constexpr int H = 512;    // value dim
constexpr int MQ = 32;    // queries per CTA
constexpr int TK = 32;    // key tile

// Scratch (allocation-free: __device__ globals)
__device__ float g_sumsq;
__device__ float g_xn[(size_t)B * N * E];   // normalized x, layout (b, n, e)

// Dynamic smem layout (floats):
//  sQ  [MQ][E]        = 8192
//  sKT [E][33]        = 8448   (transposed keys, padded to 33 for conflict-free)
//  sH  [TK][H]        = 16384
//  sW  [MQ][TK]       = 1024
//  sDen[MQ]           = 32
//  sRed[8]            = 8
constexpr int SMEM_FLOATS = MQ*E + E*33 + TK*H + MQ*TK + MQ + 8;
constexpr int SMEM_BYTES  = SMEM_FLOATS * 4;

__global__ void k_zero() { g_sumsq = 0.f; }

// One warp per row. Row order follows input layout (i*B + b).
__global__ void k_normalize(const float* __restrict__ x) {
    int row  = blockIdx.x * 8 + (threadIdx.x >> 5);
    int lane = threadIdx.x & 31;
    int i = row / B, b = row % B;
    const float4* src = (const float4*)(x + (size_t)row * E);
    float4 v0 = src[lane];
    float4 v1 = src[lane + 32];
    float s = v0.x*v0.x + v0.y*v0.y + v0.z*v0.z + v0.w*v0.w
            + v1.x*v1.x + v1.y*v1.y + v1.z*v1.z + v1.w*v1.w;
    #pragma unroll
    for (int o = 16; o; o >>= 1) s += __shfl_xor_sync(0xFFFFFFFFu, s, o);
    float r = rsqrtf(s);
    v0.x*=r; v0.y*=r; v0.z*=r; v0.w*=r;
    v1.x*=r; v1.y*=r; v1.z*=r; v1.w*=r;
    float4* dst = (float4*)(g_xn + ((size_t)b * N + i) * E);
    dst[lane]      = v0;
    dst[lane + 32] = v1;
}

extern __shared__ float smem[];

__global__ __launch_bounds__(256, 1)
void k_attn(const float* __restrict__ hh, float* __restrict__ out) {
    float* sQ   = smem;                  // [MQ][E]
    float* sKT  = sQ  + MQ * E;          // [E][33]
    float* sH   = sKT + E * 33;          // [TK][H]
    float* sW   = sH  + TK * H;          // [MQ][TK]
    float* sDen = sW  + MQ * TK;         // [MQ]
    float* sRed = sDen + MQ;             // [8]

    const int b    = blockIdx.y;
    const int q0   = blockIdx.x * MQ;
    const int t    = threadIdx.x;
    const int lane = t & 31;
    const int warp = t >> 5;
    const int qb   = warp * 4;           // 4 local query rows per warp

    // Load query tile (fp32, row-major)
    {
        int r = t >> 3, c8 = t & 7;
        const float4* src = (const float4*)(g_xn + ((size_t)b * N + q0 + r) * E);
        float4* dst = (float4*)(sQ + r * E);
        #pragma unroll
        for (int k = 0; k < 8; k++) dst[c8 + 8*k] = src[c8 + 8*k];
    }
    if (t < MQ) sDen[t] = 0.f;

    // Output accumulators: 4 query rows x 16 H-cols (as 4 float4, stride-128 interleave)
    float4 acc[4][4];
    #pragma unroll
    for (int i = 0; i < 4; i++)
        #pragma unroll
        for (int k = 0; k < 4; k++) acc[i][k] = make_float4(0.f,0.f,0.f,0.f);

    for (int j0 = 0; j0 < N; j0 += TK) {
        __syncthreads();   // previous-iteration readers done before overwriting sKT/sH

        // Load key tile TRANSPOSED: sKT[e][j], row stride 33 (conflict-free STS/LDS)
        {
            int j = t >> 3, c8 = t & 7;
            const float* src = g_xn + ((size_t)b * N + j0 + j) * E;
            #pragma unroll
            for (int k = 0; k < 8; k++) {
                int e = c8 * 4 + 32 * k;
                float4 v = *(const float4*)(src + e);
                sKT[(e+0)*33 + j] = v.x;
                sKT[(e+1)*33 + j] = v.y;
                sKT[(e+2)*33 + j] = v.z;
                sKT[(e+3)*33 + j] = v.w;
            }
        }
        // Load h tile (row-major): h layout is (N, B, H)
        {
            int j = t >> 3, c8 = t & 7;
            const float4* src = (const float4*)(hh + ((size_t)(j0 + j) * B + b) * H);
            float4* dst = (float4*)(sH + j * H);
            #pragma unroll
            for (int k = 0; k < 16; k++) dst[c8 + 8*k] = src[c8 + 8*k];
        }
        __syncthreads();

        // S-GEMM: warp -> rows qb..qb+3, lane -> key column j=lane.
        // sKT read is stride-1 across lanes (conflict-free); sQ reads are warp-uniform broadcasts.
        float s0 = 0.f, s1 = 0.f, s2 = 0.f, s3 = 0.f;
        #pragma unroll 8
        for (int e = 0; e < E; e++) {
            float kv = sKT[e*33 + lane];
            s0 += sQ[(qb+0)*E + e] * kv;
            s1 += sQ[(qb+1)*E + e] * kv;
            s2 += sQ[(qb+2)*E + e] * kv;
            s3 += sQ[(qb+3)*E + e] * kv;
        }
        // scores in [-1,1] -> exp without max subtraction
        float w0 = __expf(s0), w1 = __expf(s1), w2 = __expf(s2), w3 = __expf(s3);
        sW[(qb+0)*TK + lane] = w0;
        sW[(qb+1)*TK + lane] = w1;
        sW[(qb+2)*TK + lane] = w2;
        sW[(qb+3)*TK + lane] = w3;
        // running denominators (warp-private rows; no block sync needed)
        float r0 = w0, r1 = w1, r2 = w2, r3 = w3;
        #pragma unroll
        for (int o = 16; o; o >>= 1) {
            r0 += __shfl_xor_sync(0xFFFFFFFFu, r0, o);
            r1 += __shfl_xor_sync(0xFFFFFFFFu, r1, o);
            r2 += __shfl_xor_sync(0xFFFFFFFFu, r2, o);
            r3 += __shfl_xor_sync(0xFFFFFFFFu, r3, o);
        }
        if (lane == 0) {
            sDen[qb+0] += r0; sDen[qb+1] += r1;
            sDen[qb+2] += r2; sDen[qb+3] += r3;
        }
        __syncwarp();   // sW rows are written & read only by this warp

        // P @ h : per j, 4 broadcast weights + 4 conflict-free LDS.128 + 64 FFMA
        for (int j = 0; j < TK; j++) {
            float wq0 = sW[(qb+0)*TK + j];
            float wq1 = sW[(qb+1)*TK + j];
            float wq2 = sW[(qb+2)*TK + j];
            float wq3 = sW[(qb+3)*TK + j];
            const float* hrow = sH + j * H + 4 * lane;
            #pragma unroll
            for (int k = 0; k < 4; k++) {
                float4 hv = *(const float4*)(hrow + 128 * k);
                acc[0][k].x += wq0*hv.x; acc[0][k].y += wq0*hv.y;
                acc[0][k].z += wq0*hv.z; acc[0][k].w += wq0*hv.w;
                acc[1][k].x += wq1*hv.x; acc[1][k].y += wq1*hv.y;
                acc[1][k].z += wq1*hv.z; acc[1][k].w += wq1*hv.w;
                acc[2][k].x += wq2*hv.x; acc[2][k].y += wq2*hv.y;
                acc[2][k].z += wq2*hv.z; acc[2][k].w += wq2*hv.w;
                acc[3][k].x += wq3*hv.x; acc[3][k].y += wq3*hv.y;
                acc[3][k].z += wq3*hv.z; acc[3][k].w += wq3*hv.w;
            }
        }
    }

    __syncwarp();  // sDen written by lane 0, read by all lanes of this warp

    // Epilogue: divide by row denominator, write out (N,B,H), accumulate sumsq
    float lsum = 0.f;
    #pragma unroll
    for (int i = 0; i < 4; i++) {
        float inv = 1.f / sDen[qb + i];
        int gi = q0 + qb + i;
        float* op = out + ((size_t)gi * B + b) * H + 4 * lane;
        #pragma unroll
        for (int k = 0; k < 4; k++) {
            float4 v = acc[i][k];
            v.x *= inv; v.y *= inv; v.z *= inv; v.w *= inv;
            *(float4*)(op + 128 * k) = v;
            lsum += v.x*v.x + v.y*v.y + v.z*v.z + v.w*v.w;
        }
    }
    #pragma unroll
    for (int o = 16; o; o >>= 1) lsum += __shfl_xor_sync(0xFFFFFFFFu, lsum, o);
    if (lane == 0) sRed[warp] = lsum;
    __syncthreads();
    if (warp == 0) {
        float v = (lane < 8) ? sRed[lane] : 0.f;
        #pragma unroll
        for (int o = 4; o; o >>= 1) v += __shfl_xor_sync(0xFFFFFFFFu, v, o);
        if (lane == 0) atomicAdd(&g_sumsq, v);
    }
}

__global__ void k_scale(float* __restrict__ out) {
    float inv = rsqrtf(g_sumsq);
    int idx = blockIdx.x * blockDim.x + threadIdx.x;   // over float4s; grid sized exactly
    float4* p = (float4*)out;
    float4 v = p[idx];
    v.x *= inv; v.y *= inv; v.z *= inv; v.w *= inv;
    p[idx] = v;
}

extern "C" void kernel_launch(void* const* d_in, const int* in_sizes, int n_in,
                              void* d_out, int out_size) {
    const float* x  = (const float*)d_in[0];   // (N, B, E)
    const float* hh = (const float*)d_in[1];   // (N, B, H)
    float* out = (float*)d_out;                // (N, B, H)

    cudaFuncSetAttribute(k_attn, cudaFuncAttributeMaxDynamicSharedMemorySize, SMEM_BYTES);

    k_zero<<<1, 1>>>();
    k_normalize<<<(N * B) / 8, 256>>>(x);
    dim3 grid(N / MQ, B);
    k_attn<<<grid, 256, SMEM_BYTES>>>(hh, out);
    k_scale<<<(N * B * H / 4) / 256, 256>>>(out);
}

// round 10
// speedup vs baseline: 7.7618x; 7.7618x over previous
#include <cuda_runtime.h>
#include <cuda_fp16.h>
#include <cstdint>

// ---------------- problem constants ----------------
constexpr int N = 2048, B = 8, E = 256, H = 512;
constexpr int MQ = 64;          // queries per CTA
constexpr int TK = 32;          // keys per tile
constexpr int NT = N / TK;      // 64 tiles
constexpr int THREADS = 512;    // 16 warps

// padded smem row strides (in halves) -> conflict-free ldmatrix
constexpr int XS = 264;   // x rows: 256 + 8
constexpr int HS = 520;   // h rows: 512 + 8
constexpr int PS = 72;    // P rows: 64 + 8

// smem byte offsets
constexpr int OFF_XQ  = 0;                          // 64*264*2  = 33792
constexpr int OFF_XK  = OFF_XQ + MQ * XS * 2;       // 2 bufs of 32*264*2 = 16896
constexpr int OFF_HH  = OFF_XK + 2 * TK * XS * 2;   // 2 bufs of 32*520*2 = 33280
constexpr int OFF_P   = OFF_HH + 2 * TK * HS * 2;   // 64*72*2 = 9216
constexpr int OFF_DEN = OFF_P + MQ * PS * 2;        // 64*4 floats = 1024
constexpr int OFF_RED = OFF_DEN + 64 * 4 * 4;       // 16 floats
constexpr int SMEM_BYTES = OFF_RED + 64;            // 144448 bytes

// ---------------- device scratch ----------------
__device__ float g_sumsq;
__device__ __align__(16) __half g_xh[(size_t)B * N * E];   // normalized x fp16, (b,n,e)
__device__ __align__(16) __half g_hh[(size_t)N * B * H];   // h fp16, (n,b,hd)

// ---------------- asm helpers (all baseline-ISA, no 'a'-target features) ----
__device__ __forceinline__ uint32_t smem_u32(const void* p) {
    uint32_t a;
    asm("{ .reg .u64 t; cvta.to.shared.u64 t, %1; cvt.u32.u64 %0, t; }" : "=r"(a) : "l"(p));
    return a;
}
__device__ __forceinline__ void cpa16(uint32_t dst, const void* src) {
    asm volatile("cp.async.cg.shared.global [%0], [%1], 16;" :: "r"(dst), "l"(src));
}
#define CP_COMMIT() asm volatile("cp.async.commit_group;" ::: "memory")
#define CP_WAIT1()  asm volatile("cp.async.wait_group 1;" ::: "memory")
#define CP_WAIT0()  asm volatile("cp.async.wait_group 0;" ::: "memory")

#define LDSM4(r0,r1,r2,r3,a) \
    asm volatile("ldmatrix.sync.aligned.m8n8.x4.shared.b16 {%0,%1,%2,%3}, [%4];" \
        : "=r"(r0),"=r"(r1),"=r"(r2),"=r"(r3) : "r"(a))
#define LDSM2(r0,r1,a) \
    asm volatile("ldmatrix.sync.aligned.m8n8.x2.shared.b16 {%0,%1}, [%2];" \
        : "=r"(r0),"=r"(r1) : "r"(a))
#define LDSM4T(r0,r1,r2,r3,a) \
    asm volatile("ldmatrix.sync.aligned.m8n8.x4.trans.shared.b16 {%0,%1,%2,%3}, [%4];" \
        : "=r"(r0),"=r"(r1),"=r"(r2),"=r"(r3) : "r"(a))

#define MMA(c, a0,a1,a2,a3, b0,b1) \
    asm volatile("mma.sync.aligned.m16n8k16.row.col.f32.f16.f16.f32 " \
        "{%0,%1,%2,%3}, {%4,%5,%6,%7}, {%8,%9}, {%0,%1,%2,%3};" \
        : "+f"((c)[0]),"+f"((c)[1]),"+f"((c)[2]),"+f"((c)[3]) \
        : "r"(a0),"r"(a1),"r"(a2),"r"(a3),"r"(b0),"r"(b1))

// ---------------- aux kernels ----------------
__global__ void k_zero() { g_sumsq = 0.f; }

// One warp per (n,b) row: L2-normalize x, store fp16 into (b,n,e)
__global__ void k_normalize(const float* __restrict__ x) {
    int row  = blockIdx.x * 8 + (threadIdx.x >> 5);
    int lane = threadIdx.x & 31;
    int i = row / B, bb = row % B;
    const float4* src = (const float4*)(x + (size_t)row * E);
    float4 v0 = src[lane], v1 = src[lane + 32];
    float s = v0.x*v0.x + v0.y*v0.y + v0.z*v0.z + v0.w*v0.w
            + v1.x*v1.x + v1.y*v1.y + v1.z*v1.z + v1.w*v1.w;
    #pragma unroll
    for (int o = 16; o; o >>= 1) s += __shfl_xor_sync(0xFFFFFFFFu, s, o);
    float r = rsqrtf(s);
    __half2* dst = (__half2*)(g_xh + ((size_t)bb * N + i) * E);
    dst[2*lane]          = __floats2half2_rn(v0.x*r, v0.y*r);
    dst[2*lane + 1]      = __floats2half2_rn(v0.z*r, v0.w*r);
    dst[2*(lane+32)]     = __floats2half2_rn(v1.x*r, v1.y*r);
    dst[2*(lane+32) + 1] = __floats2half2_rn(v1.z*r, v1.w*r);
}

// Elementwise h fp32 -> fp16 (same (n,b,hd) layout); 8 elems per thread
__global__ void k_convh(const float* __restrict__ hh) {
    size_t gid = (size_t)blockIdx.x * 256 + threadIdx.x;
    const float4* s = (const float4*)hh;
    float4 a = s[gid * 2], c = s[gid * 2 + 1];
    __half2 o[4] = { __floats2half2_rn(a.x, a.y), __floats2half2_rn(a.z, a.w),
                     __floats2half2_rn(c.x, c.y), __floats2half2_rn(c.z, c.w) };
    *(uint4*)(g_hh + gid * 8) = *(uint4*)o;
}

// ---------------- tile loader (cp.async) ----------------
__device__ __forceinline__ void load_tile(uint32_t sb, const __half* xb, int b,
                                          int tt, int bi) {
    const int t = threadIdx.x;
    const int j0 = tt * TK;
    const uint32_t XKb = sb + OFF_XK + bi * (TK * XS * 2);
    const uint32_t HHb = sb + OFF_HH + bi * (TK * HS * 2);
    #pragma unroll
    for (int k = 0; k < 2; k++) {            // Xk: 32 rows x 32 chunks
        int i = t + k * THREADS;
        int r = i >> 5, ch = i & 31;
        cpa16(XKb + r * (XS*2) + ch * 16, xb + (size_t)(j0 + r) * E + ch * 8);
    }
    #pragma unroll
    for (int k = 0; k < 4; k++) {            // h: 32 rows x 64 chunks
        int i = t + k * THREADS;
        int r = i >> 6, ch = i & 63;
        cpa16(HHb + r * (HS*2) + ch * 16,
              g_hh + ((size_t)(j0 + r) * B + b) * (size_t)H + ch * 8);
    }
}

// ---------------- main fused attention ----------------
__global__ __launch_bounds__(THREADS, 1)
void k_attn(float* __restrict__ out) {
    extern __shared__ char smem[];
    const uint32_t sb = smem_u32(smem);
    const int t = threadIdx.x, lane = t & 31, warp = t >> 5;
    const int b = blockIdx.y, q0 = blockIdx.x * MQ;
    const __half* xb = g_xh + (size_t)b * N * E;

    const int swr = warp >> 2, swc = warp & 3;   // S phase: 4x4 warp grid (16q x 8k each)
    const int rg  = warp >> 3, cg  = warp & 7;   // P@h:     2x8 warp grid (32q x 64h each)

    if (t < 256) ((float*)(smem + OFF_DEN))[t] = 0.f;

    // prologue: Xq + tile0 (group 0), tile1 (group 1)
    #pragma unroll
    for (int k = 0; k < 4; k++) {                // Xq: 64 rows x 32 chunks
        int i = t + k * THREADS;
        int r = i >> 5, ch = i & 31;
        cpa16(sb + OFF_XQ + r * (XS*2) + ch * 16, xb + (size_t)(q0 + r) * E + ch * 8);
    }
    load_tile(sb, xb, b, 0, 0);
    CP_COMMIT();
    load_tile(sb, xb, b, 1, 1);
    CP_COMMIT();

    float acc[2][8][4];
    #pragma unroll
    for (int mt = 0; mt < 2; mt++)
        #pragma unroll
        for (int nt = 0; nt < 8; nt++)
            #pragma unroll
            for (int e = 0; e < 4; e++) acc[mt][nt][e] = 0.f;

    for (int tt = 0; tt < NT; ++tt) {
        const int bi = tt & 1;
        if (tt < NT - 1) { CP_WAIT1(); } else { CP_WAIT0(); }
        __syncthreads();

        const uint32_t XKb = sb + OFF_XK + bi * (TK * XS * 2);
        const uint32_t HHb = sb + OFF_HH + bi * (TK * HS * 2);

        // ---- S = Xq @ Xk^T : warp tile 16q x 8k, K=256 (16 k-steps)
        float c[4] = {0.f, 0.f, 0.f, 0.f};
        {
            const uint32_t aB = sb + OFF_XQ
                + (uint32_t)(16*swr + (lane & 15)) * (XS*2) + (uint32_t)(lane >> 4) * 16;
            const uint32_t bB = XKb
                + (uint32_t)(8*swc + (lane & 7)) * (XS*2) + (uint32_t)((lane >> 3) & 1) * 16;
            #pragma unroll
            for (int ks = 0; ks < 16; ks++) {
                uint32_t a0,a1,a2,a3,b0,b1;
                LDSM4(a0,a1,a2,a3, aB + ks * 32);
                LDSM2(b0,b1,       bB + ks * 32);
                MMA(c, a0,a1,a2,a3, b0,b1);
            }
        }
        // exp (scores in [-1,1]: no max-sub), running denominator, store P fp16
        {
            float w0 = __expf(c[0]), w1 = __expf(c[1]);
            float w2 = __expf(c[2]), w3 = __expf(c[3]);
            float d0 = w0 + w1, d1 = w2 + w3;
            #pragma unroll
            for (int o = 1; o <= 2; o <<= 1) {
                d0 += __shfl_xor_sync(0xFFFFFFFFu, d0, o);
                d1 += __shfl_xor_sync(0xFFFFFFFFu, d1, o);
            }
            int prow = 16*swr + (lane >> 2);
            int pcol = (8*swc + 2*(lane & 3)) * 2;
            *(__half2*)(smem + OFF_P + prow * (PS*2) + pcol)       = __floats2half2_rn(w0, w1);
            *(__half2*)(smem + OFF_P + (prow + 8) * (PS*2) + pcol) = __floats2half2_rn(w2, w3);
            if ((lane & 3) == 0) {
                float* dp = (float*)(smem + OFF_DEN);
                dp[prow * 4 + swc]       += d0;
                dp[(prow + 8) * 4 + swc] += d1;
            }
        }
        __syncthreads();

        // ---- O += P @ Htile : warp tile 32q x 64h, K=32 (2 k-steps)
        #pragma unroll
        for (int ks = 0; ks < 2; ks++) {
            uint32_t a[2][4];
            #pragma unroll
            for (int mt = 0; mt < 2; mt++)
                LDSM4(a[mt][0],a[mt][1],a[mt][2],a[mt][3],
                    sb + OFF_P + (uint32_t)(32*rg + 16*mt + (lane & 15)) * (PS*2)
                               + (uint32_t)(ks*16 + (lane >> 4) * 8) * 2);
            #pragma unroll
            for (int q = 0; q < 4; q++) {
                uint32_t r0,r1,r2,r3;
                LDSM4T(r0,r1,r2,r3,
                    HHb + (uint32_t)(ks*16 + (lane & 15)) * (HS*2)
                        + (uint32_t)(64*cg + 16*q + (lane >> 4) * 8) * 2);
                #pragma unroll
                for (int mt = 0; mt < 2; mt++) {
                    MMA(acc[mt][2*q],     a[mt][0],a[mt][1],a[mt][2],a[mt][3], r0, r1);
                    MMA(acc[mt][2*q + 1], a[mt][0],a[mt][1],a[mt][2],a[mt][3], r2, r3);
                }
            }
        }
        __syncthreads();
        if (tt + 2 < NT) { load_tile(sb, xb, b, tt + 2, bi); CP_COMMIT(); }
    }

    // ---- epilogue: divide by den, write out, accumulate global sumsq
    float lss = 0.f;
    #pragma unroll
    for (int mt = 0; mt < 2; mt++) {
        #pragma unroll
        for (int s = 0; s < 2; s++) {
            int row = 32*rg + 16*mt + (lane >> 2) + 8*s;
            float4 dv = *(const float4*)(smem + OFF_DEN + row * 16);
            float inv = 1.f / (dv.x + dv.y + dv.z + dv.w);
            float* op = out + ((size_t)(q0 + row) * B + b) * H + 64*cg + 2*(lane & 3);
            #pragma unroll
            for (int nt = 0; nt < 8; nt++) {
                float v0 = acc[mt][nt][2*s]     * inv;
                float v1 = acc[mt][nt][2*s + 1] * inv;
                lss += v0*v0 + v1*v1;
                *(float2*)(op + 8*nt) = make_float2(v0, v1);
            }
        }
    }
    #pragma unroll
    for (int o = 16; o; o >>= 1) lss += __shfl_xor_sync(0xFFFFFFFFu, lss, o);
    if (lane == 0) ((float*)(smem + OFF_RED))[warp] = lss;
    __syncthreads();
    if (warp == 0) {
        float v = (lane < 16) ? ((float*)(smem + OFF_RED))[lane] : 0.f;
        #pragma unroll
        for (int o = 8; o; o >>= 1) v += __shfl_xor_sync(0xFFFFFFFFu, v, o);
        if (lane == 0) atomicAdd(&g_sumsq, v);
    }
}

__global__ void k_scale(float* __restrict__ out) {
    float inv = rsqrtf(g_sumsq);
    int idx = blockIdx.x * blockDim.x + threadIdx.x;
    float4* p = (float4*)out;
    float4 v = p[idx];
    v.x *= inv; v.y *= inv; v.z *= inv; v.w *= inv;
    p[idx] = v;
}

extern "C" void kernel_launch(void* const* d_in, const int* in_sizes, int n_in,
                              void* d_out, int out_size) {
    const float* x  = (const float*)d_in[0];   // (N, B, E)
    const float* hh = (const float*)d_in[1];   // (N, B, H)
    float* out = (float*)d_out;                // (N, B, H)

    cudaFuncSetAttribute(k_attn, cudaFuncAttributeMaxDynamicSharedMemorySize, SMEM_BYTES);

    k_zero<<<1, 1>>>();
    k_normalize<<<(N * B) / 8, 256>>>(x);
    k_convh<<<(int)(((size_t)N * B * H / 8) / 256), 256>>>(hh);
    k_attn<<<dim3(N / MQ, B), THREADS, SMEM_BYTES>>>(out);
    k_scale<<<(N * B * H / 4) / 256, 256>>>(out);
}